// round 13
// baseline (speedup 1.0000x reference)
#include <cuda_runtime.h>
#include <cuda_bf16.h>
#include <cstdint>

#define BB   2
#define SS   2048
#define DD   1024
#define HH   16
#define HD   64
#define MROWS (BB*SS)   // 4096

// ---------------------------------------------------------------------------
// Scratch (__device__ globals; no allocation allowed)
// ---------------------------------------------------------------------------
__device__ float g_q[MROWS*DD];
__device__ float g_k[MROWS*DD];
__device__ float g_v[MROWS*DD];
__device__ __nv_bfloat16 g_xhi[MROWS*DD];
__device__ __nv_bfloat16 g_xlo[MROWS*DD];
__device__ __nv_bfloat16 g_whi[4*DD*DD];
__device__ __nv_bfloat16 g_wlo[4*DD*DD];
__device__ __nv_bfloat16 g_atthi[MROWS*DD];
__device__ __nv_bfloat16 g_attlo[MROWS*DD];
// flash operands
__device__ __nv_bfloat16 g_qhi[MROWS*DD];
__device__ __nv_bfloat16 g_qlo[MROWS*DD];
__device__ __nv_bfloat16 g_khi[MROWS*DD];
__device__ __nv_bfloat16 g_klo[MROWS*DD];
__device__ __nv_bfloat16 g_vthi[MROWS*DD];   // [(b*HH+h)*HD + d][s]
__device__ __nv_bfloat16 g_vtlo[MROWS*DD];

// ---------------------------------------------------------------------------
// PTX helpers (baseline ISA only — valid for plain sm_103 target)
// ---------------------------------------------------------------------------
__device__ __forceinline__ uint32_t smem_u32(const void* p) {
    uint32_t a;
    asm("{ .reg .u64 t; cvta.to.shared.u64 t, %1; cvt.u32.u64 %0, t; }" : "=r"(a) : "l"(p));
    return a;
}
__device__ __forceinline__ void cpa16(uint32_t saddr, const void* g) {
    asm volatile("cp.async.cg.shared.global [%0], [%1], 16;" :: "r"(saddr), "l"(g));
}
#define CP_COMMIT() asm volatile("cp.async.commit_group;" ::: "memory")
#define CP_WAIT0()  asm volatile("cp.async.wait_group 0;" ::: "memory")
#define CP_WAIT3()  asm volatile("cp.async.wait_group 3;" ::: "memory")

__device__ __forceinline__ void ldsm_x4(uint32_t& r0, uint32_t& r1, uint32_t& r2,
                                        uint32_t& r3, uint32_t a) {
    asm volatile("ldmatrix.sync.aligned.m8n8.x4.shared.b16 {%0,%1,%2,%3}, [%4];"
                 : "=r"(r0), "=r"(r1), "=r"(r2), "=r"(r3) : "r"(a));
}
__device__ __forceinline__ void ldsm_x2(uint32_t& r0, uint32_t& r1, uint32_t a) {
    asm volatile("ldmatrix.sync.aligned.m8n8.x2.shared.b16 {%0,%1}, [%2];"
                 : "=r"(r0), "=r"(r1) : "r"(a));
}
__device__ __forceinline__ void mma16816(float* c, uint32_t a0, uint32_t a1,
                                         uint32_t a2, uint32_t a3,
                                         uint32_t b0, uint32_t b1) {
    asm volatile(
        "mma.sync.aligned.m16n8k16.row.col.f32.bf16.bf16.f32 "
        "{%0,%1,%2,%3}, {%4,%5,%6,%7}, {%8,%9}, {%0,%1,%2,%3};"
        : "+f"(c[0]), "+f"(c[1]), "+f"(c[2]), "+f"(c[3])
        : "r"(a0), "r"(a1), "r"(a2), "r"(a3), "r"(b0), "r"(b1));
}
__device__ __forceinline__ float exp2_(float x) {
    float y; asm("ex2.approx.f32 %0, %1;" : "=f"(y) : "f"(x)); return y;
}

// ---------------------------------------------------------------------------
// Split fp32 -> bf16 hi + bf16 lo
// ---------------------------------------------------------------------------
__device__ __forceinline__ void split4(const float* __restrict__ in,
                                       __nv_bfloat16* __restrict__ hi,
                                       __nv_bfloat16* __restrict__ lo, int i)
{
    float4 v = ((const float4*)in)[i];
    __nv_bfloat16 hx = __float2bfloat16(v.x);
    __nv_bfloat16 hy = __float2bfloat16(v.y);
    __nv_bfloat16 hz = __float2bfloat16(v.z);
    __nv_bfloat16 hw = __float2bfloat16(v.w);
    __nv_bfloat16 lx = __float2bfloat16(v.x - __bfloat162float(hx));
    __nv_bfloat16 ly = __float2bfloat16(v.y - __bfloat162float(hy));
    __nv_bfloat16 lz = __float2bfloat16(v.z - __bfloat162float(hz));
    __nv_bfloat16 lw = __float2bfloat16(v.w - __bfloat162float(hw));
    ((__nv_bfloat162*)hi)[2*i]   = __halves2bfloat162(hx, hy);
    ((__nv_bfloat162*)hi)[2*i+1] = __halves2bfloat162(hz, hw);
    ((__nv_bfloat162*)lo)[2*i]   = __halves2bfloat162(lx, ly);
    ((__nv_bfloat162*)lo)[2*i+1] = __halves2bfloat162(lz, lw);
}

__global__ __launch_bounds__(256) void split_kernel(
    const float* __restrict__ in, __nv_bfloat16* __restrict__ hi,
    __nv_bfloat16* __restrict__ lo, int n4)
{
    int i = blockIdx.x * blockDim.x + threadIdx.x;
    if (i >= n4) return;
    split4(in, hi, lo, i);
}

// All 4 weight matrices in one launch: grid (DD*DD/4/256, 4)
__global__ __launch_bounds__(256) void wsplit_kernel(
    const float* __restrict__ w0, const float* __restrict__ w1,
    const float* __restrict__ w2, const float* __restrict__ w3,
    __nv_bfloat16* __restrict__ hi, __nv_bfloat16* __restrict__ lo)
{
    int z = blockIdx.y;
    const float* w = (z == 0) ? w0 : (z == 1) ? w1 : (z == 2) ? w2 : w3;
    int i = blockIdx.x * blockDim.x + threadIdx.x;
    split4(w, hi + (size_t)z * DD * DD, lo + (size_t)z * DD * DD, i);
}

// ---------------------------------------------------------------------------
// Warp-mma bf16 split GEMM: C = Ah*Bh + Ah*Bl + Al*Bh + bias
// CTA tile 128x128, KC=32, 4-stage cp.async ring, 8 warps, warp tile 64x32.
// Fragments loaded once per kk, reused across split terms; B via ldsm_x4.
// ---------------------------------------------------------------------------
#define KC      32
#define APAD    40
#define TILE_E  (128*APAD)
#define STAGE_E (4*TILE_E)
#define NSLOT   4
#define GEMM_SMEM_BYTES (NSLOT*STAGE_E*2)   // 163840 B
#define NSTAGES (DD/KC)                     // 32

__device__ __forceinline__ void ld_tile(
    uint32_t s_elem_base, const __nv_bfloat16* __restrict__ g,
    int rowbase, int k0, int tid, uint32_t smem_base_u32)
{
    #pragma unroll
    for (int t = 0; t < 2; t++) {
        int v   = tid + t * 256;
        int row = v >> 2;
        int c   = v & 3;
        uint32_t sa = smem_base_u32 + (s_elem_base + (uint32_t)(row * APAD + c * 8)) * 2;
        const void* ga = g + (size_t)(rowbase + row) * DD + k0 + c * 8;
        cpa16(sa, ga);
    }
}

__device__ __forceinline__ void load_stage(
    uint32_t smem_base_u32, int slot,
    const __nv_bfloat16* Ah, const __nv_bfloat16* Al,
    const __nv_bfloat16* Bh, const __nv_bfloat16* Bl,
    int bm, int bn, int k0, int tid)
{
    uint32_t sb = (uint32_t)slot * STAGE_E;
    ld_tile(sb,             Ah, bm, k0, tid, smem_base_u32);
    ld_tile(sb +   TILE_E,  Al, bm, k0, tid, smem_base_u32);
    ld_tile(sb + 2*TILE_E,  Bh, bn, k0, tid, smem_base_u32);
    ld_tile(sb + 3*TILE_E,  Bl, bn, k0, tid, smem_base_u32);
    CP_COMMIT();
}

__device__ __forceinline__ void gemm_body(
    const __nv_bfloat16* __restrict__ Ahg, const __nv_bfloat16* __restrict__ Alg,
    const __nv_bfloat16* __restrict__ Bhg, const __nv_bfloat16* __restrict__ Blg,
    const float* __restrict__ bias, float* __restrict__ C, int bm, int bn)
{
    extern __shared__ __nv_bfloat16 sm[];
    const uint32_t smb = smem_u32(sm);

    const int tid  = threadIdx.x;
    const int lane = tid & 31;
    const int wid  = tid >> 5;
    const int m0   = (wid >> 2) * 64;
    const int n0   = (wid & 3) * 32;

    // A ldsm lane mapping (x4: 16 rows x 16 k)
    const int g3   = lane >> 3;
    const int lr   = lane & 7;
    const int arow = lr + ((g3 & 1) << 3);
    const int akof = (g3 & 2) << 2;
    // B ldsm_x4 lane mapping: lanes 0-15 -> n-tile np*2, lanes 16-31 -> np*2+1
    const int brow = ((lane >> 4) << 3) + lr;       // + nt*8 base added per load
    const int bkof = ((lane >> 3) & 1) << 3;

    float acc[4][4][4];
    #pragma unroll
    for (int mt = 0; mt < 4; mt++)
        #pragma unroll
        for (int nt = 0; nt < 4; nt++)
            #pragma unroll
            for (int r = 0; r < 4; r++) acc[mt][nt][r] = 0.f;

    load_stage(smb, 0, Ahg, Alg, Bhg, Blg, bm, bn, 0, tid);
    load_stage(smb, 1, Ahg, Alg, Bhg, Blg, bm, bn, KC, tid);
    load_stage(smb, 2, Ahg, Alg, Bhg, Blg, bm, bn, 2 * KC, tid);

    for (int s = 0; s < NSTAGES; s++) {
        __syncthreads();     // all warps done reading slot (s-1)&3 (overwritten below)
        if (s + 3 < NSTAGES)
            load_stage(smb, (s + 3) & 3, Ahg, Alg, Bhg, Blg, bm, bn, (s + 3) * KC, tid);
        else
            CP_COMMIT();     // keep group count uniform
        CP_WAIT3();          // stage s resident
        __syncthreads();

        const uint32_t stb = smb + (uint32_t)(s & 3) * STAGE_E * 2;
        const uint32_t tAh = stb;
        const uint32_t tAl = stb + TILE_E * 2;
        const uint32_t tBh = stb + 2 * TILE_E * 2;
        const uint32_t tBl = stb + 3 * TILE_E * 2;

        #pragma unroll
        for (int kk = 0; kk < 2; kk++) {
            const int ak = kk * 16 + akof;
            const int bk = kk * 16 + bkof;

            uint32_t Ah[4][4], Al[4][4], Bh[4][2], Bl[4][2];
            #pragma unroll
            for (int mt = 0; mt < 4; mt++) {
                uint32_t ao = (uint32_t)((m0 + mt*16 + arow) * APAD + ak) * 2;
                ldsm_x4(Ah[mt][0], Ah[mt][1], Ah[mt][2], Ah[mt][3], tAh + ao);
                ldsm_x4(Al[mt][0], Al[mt][1], Al[mt][2], Al[mt][3], tAl + ao);
            }
            #pragma unroll
            for (int np = 0; np < 2; np++) {
                uint32_t bo = (uint32_t)((n0 + np*16 + brow) * APAD + bk) * 2;
                ldsm_x4(Bh[2*np][0], Bh[2*np][1], Bh[2*np+1][0], Bh[2*np+1][1], tBh + bo);
                ldsm_x4(Bl[2*np][0], Bl[2*np][1], Bl[2*np+1][0], Bl[2*np+1][1], tBl + bo);
            }

            #pragma unroll
            for (int mt = 0; mt < 4; mt++)
                #pragma unroll
                for (int nt = 0; nt < 4; nt++)
                    mma16816(acc[mt][nt], Ah[mt][0], Ah[mt][1], Ah[mt][2], Ah[mt][3],
                             Bh[nt][0], Bh[nt][1]);
            #pragma unroll
            for (int mt = 0; mt < 4; mt++)
                #pragma unroll
                for (int nt = 0; nt < 4; nt++)
                    mma16816(acc[mt][nt], Al[mt][0], Al[mt][1], Al[mt][2], Al[mt][3],
                             Bh[nt][0], Bh[nt][1]);
            #pragma unroll
            for (int mt = 0; mt < 4; mt++)
                #pragma unroll
                for (int nt = 0; nt < 4; nt++)
                    mma16816(acc[mt][nt], Ah[mt][0], Ah[mt][1], Ah[mt][2], Ah[mt][3],
                             Bl[nt][0], Bl[nt][1]);
        }
    }

    const int gid = lane >> 2;
    const int tig = lane & 3;
    #pragma unroll
    for (int mt = 0; mt < 4; mt++) {
        #pragma unroll
        for (int nt = 0; nt < 4; nt++) {
            const float* a = acc[mt][nt];
            int r0 = bm + m0 + mt * 16 + gid;
            int cc = bn + n0 + nt * 8 + tig * 2;
            float b0 = bias[cc], b1 = bias[cc + 1];
            *(float2*)&C[(size_t)r0 * DD + cc] = make_float2(a[0] + b0, a[1] + b1);
            *(float2*)&C[(size_t)(r0 + 8) * DD + cc] = make_float2(a[2] + b0, a[3] + b1);
        }
    }
}

__global__ __launch_bounds__(256, 1) void qkv_gemm(
    const float* __restrict__ bq, const float* __restrict__ bk,
    const float* __restrict__ bv)
{
    const int z = blockIdx.z;
    const __nv_bfloat16* Bh = &g_whi[(size_t)z * DD * DD];
    const __nv_bfloat16* Bl = &g_wlo[(size_t)z * DD * DD];
    const float* bias = (z == 0) ? bq : (z == 1) ? bk : bv;
    float* C = (z == 0) ? g_q : (z == 1) ? g_k : g_v;
    gemm_body(g_xhi, g_xlo, Bh, Bl, bias, C, blockIdx.y * 128, blockIdx.x * 128);
}

__global__ __launch_bounds__(256, 1) void out_gemm(
    const float* __restrict__ bo, float* __restrict__ out)
{
    gemm_body(g_atthi, g_attlo, &g_whi[(size_t)3 * DD * DD], &g_wlo[(size_t)3 * DD * DD],
              bo, out, blockIdx.y * 128, blockIdx.x * 128);
}

// ---------------------------------------------------------------------------
// RoPE + bf16 hi/lo split of q,k. q pre-scaled by 1/sqrt(hd) * log2(e).
// ---------------------------------------------------------------------------
#define QSCALE 0.180336880111120429f   // 0.125 * log2(e)

__global__ __launch_bounds__(256) void rope_split_kernel(
    const float* __restrict__ pcos, const float* __restrict__ psin)
{
    int idx = blockIdx.x * blockDim.x + threadIdx.x;   // 0 .. MROWS*512-1
    int n   = idx >> 9;
    int pid = idx & 511;
    int srow = n & (SS - 1);
    int f    = pid & 31;
    float c  = pcos[srow * 32 + f];
    float sn = psin[srow * 32 + f];
    size_t off = ((size_t)n << 9) + pid;   // float2-pair index

    float2 qv = ((const float2*)g_q)[off];
    float qr = fmaf(qv.x, c, -qv.y * sn) * QSCALE;
    float qi = fmaf(qv.x, sn,  qv.y * c) * QSCALE;
    __nv_bfloat16 qh0 = __float2bfloat16(qr), qh1 = __float2bfloat16(qi);
    __nv_bfloat16 ql0 = __float2bfloat16(qr - __bfloat162float(qh0));
    __nv_bfloat16 ql1 = __float2bfloat16(qi - __bfloat162float(qh1));
    ((__nv_bfloat162*)g_qhi)[off] = __halves2bfloat162(qh0, qh1);
    ((__nv_bfloat162*)g_qlo)[off] = __halves2bfloat162(ql0, ql1);

    float2 kv = ((const float2*)g_k)[off];
    float kr = fmaf(kv.x, c, -kv.y * sn);
    float ki = fmaf(kv.x, sn,  kv.y * c);
    __nv_bfloat16 kh0 = __float2bfloat16(kr), kh1 = __float2bfloat16(ki);
    __nv_bfloat16 kl0 = __float2bfloat16(kr - __bfloat162float(kh0));
    __nv_bfloat16 kl1 = __float2bfloat16(ki - __bfloat162float(kh1));
    ((__nv_bfloat162*)g_khi)[off] = __halves2bfloat162(kh0, kh1);
    ((__nv_bfloat162*)g_klo)[off] = __halves2bfloat162(kl0, kl1);
}

// ---------------------------------------------------------------------------
// V transpose + split: g_v[b][s][h*64+d] -> g_vt{hi,lo}[(b*HH+h)*64+d][s]
// ---------------------------------------------------------------------------
__global__ __launch_bounds__(256) void vsplitT_kernel()
{
    __shared__ float t[32][33];
    const int s0 = blockIdx.x * 32;
    const int d0 = blockIdx.y * 32;
    const int bh = blockIdx.z;
    const int b  = bh >> 4;
    const int h  = bh & 15;
    const int lane = threadIdx.x;
    const int wr   = threadIdx.y;

    #pragma unroll
    for (int i = 0; i < 4; i++) {
        int row = wr + i * 8;
        t[row][lane] = g_v[((size_t)(b * SS + s0 + row)) * DD + h * HD + d0 + lane];
    }
    __syncthreads();
    #pragma unroll
    for (int i = 0; i < 4; i++) {
        int drow = wr + i * 8;
        float v = t[lane][drow];
        __nv_bfloat16 hv = __float2bfloat16(v);
        __nv_bfloat16 lv = __float2bfloat16(v - __bfloat162float(hv));
        size_t oa = ((size_t)(bh * HD + d0 + drow)) * SS + s0 + lane;
        g_vthi[oa] = hv;
        g_vtlo[oa] = lv;
    }
}

// ---------------------------------------------------------------------------
// Flash attention via m16n8k16 bf16-split mma (proven R12).
// ---------------------------------------------------------------------------
#define FPAD   72
#define FSM_Q   0
#define FSM_QL  9216
#define FSM_KV  18432
#define KVS     4608
#define FSM_P   55296
#define FSM_PL  64512
#define FLASH_SMEM_BYTES ((64512 + 9216) * 2)   // 147456

__global__ __launch_bounds__(256, 1) void flash_mma_kernel()
{
    extern __shared__ __nv_bfloat16 fsm[];
    const uint32_t smb = smem_u32(fsm);
    const int tid  = threadIdx.x;
    const int lane = tid & 31;
    const int wid  = tid >> 5;
    const int mblk = (int)(gridDim.x - 1) - (int)blockIdx.x;
    const int h    = blockIdx.y;
    const int b    = blockIdx.z;

    {
        const size_t qoff = ((size_t)(b * SS + mblk * 128)) * DD + h * HD;
        #pragma unroll
        for (int i = 0; i < 8; i++) {
            int v = tid + i * 256;
            const __nv_bfloat16* src = (v < 1024) ? g_qhi : g_qlo;
            int idx = v & 1023, row = idx >> 3, c = idx & 7;
            uint32_t sa = smb + (uint32_t)((v >> 10) * 9216 + row * FPAD + c * 8) * 2;
            cpa16(sa, src + qoff + (size_t)row * DD + c * 8);
        }
    }

    const int T = 2 * mblk + 2;

    auto load_kv = [&](int t, int st) {
        const int n0 = t * 64;
        const uint32_t sb = smb + (uint32_t)(FSM_KV + st * 4 * KVS) * 2;
        const size_t koff = ((size_t)(b * SS + n0)) * DD + h * HD;
        const size_t voff = ((size_t)((b * HH + h) * HD)) * SS + n0;
        #pragma unroll
        for (int i = 0; i < 8; i++) {
            int v = tid + i * 256;
            int arr = v >> 9, idx = v & 511, row = idx >> 3, c = idx & 7;
            uint32_t sa = sb + (uint32_t)(arr * KVS + row * FPAD + c * 8) * 2;
            const __nv_bfloat16* g;
            size_t ga;
            if (arr == 0)      { g = g_khi;  ga = koff + (size_t)row * DD + c * 8; }
            else if (arr == 1) { g = g_klo;  ga = koff + (size_t)row * DD + c * 8; }
            else if (arr == 2) { g = g_vthi; ga = voff + (size_t)row * SS + c * 8; }
            else               { g = g_vtlo; ga = voff + (size_t)row * SS + c * 8; }
            cpa16(sa, g + ga);
        }
        CP_COMMIT();
    };

    load_kv(0, 0);

    const int g3   = lane >> 3;
    const int lr   = lane & 7;
    const int arow = lr + ((g3 & 1) << 3);
    const int akof = (g3 & 2) << 2;
    const int bkof = ((lane >> 3) & 1) << 3;
    const int gid  = lane >> 2;
    const int tig  = lane & 3;
    const int m0   = wid * 16;
    const int qi0  = mblk * 128 + m0 + gid;

    float oacc[8][4];
    #pragma unroll
    for (int nt = 0; nt < 8; nt++)
        #pragma unroll
        for (int r = 0; r < 4; r++) oacc[nt][r] = 0.f;
    float mrow0 = -1e30f, mrow1 = -1e30f, lsum0 = 0.f, lsum1 = 0.f;

    const uint32_t bq  = smb;
    const uint32_t bql = smb + (uint32_t)FSM_QL * 2;
    const uint32_t bph = smb + (uint32_t)FSM_P * 2;
    const uint32_t bpl = smb + (uint32_t)FSM_PL * 2;

    for (int t = 0; t < T; t++) {
        CP_WAIT0();
        __syncthreads();
        const int st = t & 1;
        const uint32_t sb  = smb + (uint32_t)(FSM_KV + st * 4 * KVS) * 2;
        const uint32_t bkh = sb;
        const uint32_t bkl = sb + (uint32_t)KVS * 2;
        const uint32_t bvh = sb + (uint32_t)(2 * KVS) * 2;
        const uint32_t bvl = sb + (uint32_t)(3 * KVS) * 2;

        float sacc[8][4];
        #pragma unroll
        for (int nt = 0; nt < 8; nt++)
            #pragma unroll
            for (int r = 0; r < 4; r++) sacc[nt][r] = 0.f;

        #pragma unroll
        for (int kk = 0; kk < 4; kk++) {
            uint32_t aoff = (uint32_t)((m0 + arow) * FPAD + kk * 16 + akof) * 2;
            uint32_t Ah[4], Al[4];
            ldsm_x4(Ah[0], Ah[1], Ah[2], Ah[3], bq  + aoff);
            ldsm_x4(Al[0], Al[1], Al[2], Al[3], bql + aoff);
            #pragma unroll
            for (int nt = 0; nt < 8; nt++) {
                uint32_t boff = (uint32_t)((nt * 8 + lr) * FPAD + kk * 16 + bkof) * 2;
                uint32_t bh0, bh1, bl0, bl1;
                ldsm_x2(bh0, bh1, bkh + boff);
                ldsm_x2(bl0, bl1, bkl + boff);
                mma16816(sacc[nt], Ah[0], Ah[1], Ah[2], Ah[3], bh0, bh1);
                mma16816(sacc[nt], Ah[0], Ah[1], Ah[2], Ah[3], bl0, bl1);
                mma16816(sacc[nt], Al[0], Al[1], Al[2], Al[3], bh0, bh1);
            }
        }

        if (t + 1 < T) load_kv(t + 1, st ^ 1);

        const int n0 = t * 64;
        if (t >= 2 * mblk) {
            #pragma unroll
            for (int nt = 0; nt < 8; nt++) {
                int c0 = n0 + nt * 8 + tig * 2;
                if (c0     > qi0)     sacc[nt][0] = -1e30f;
                if (c0 + 1 > qi0)     sacc[nt][1] = -1e30f;
                if (c0     > qi0 + 8) sacc[nt][2] = -1e30f;
                if (c0 + 1 > qi0 + 8) sacc[nt][3] = -1e30f;
            }
        }

        float r0 = -1e30f, r1 = -1e30f;
        #pragma unroll
        for (int nt = 0; nt < 8; nt++) {
            r0 = fmaxf(r0, fmaxf(sacc[nt][0], sacc[nt][1]));
            r1 = fmaxf(r1, fmaxf(sacc[nt][2], sacc[nt][3]));
        }
        r0 = fmaxf(r0, __shfl_xor_sync(0xffffffffu, r0, 1));
        r0 = fmaxf(r0, __shfl_xor_sync(0xffffffffu, r0, 2));
        r1 = fmaxf(r1, __shfl_xor_sync(0xffffffffu, r1, 1));
        r1 = fmaxf(r1, __shfl_xor_sync(0xffffffffu, r1, 2));
        float m0n = fmaxf(mrow0, r0), m1n = fmaxf(mrow1, r1);
        float al0 = exp2_(mrow0 - m0n), al1 = exp2_(mrow1 - m1n);
        mrow0 = m0n; mrow1 = m1n;

        float sum0 = 0.f, sum1 = 0.f;
        #pragma unroll
        for (int nt = 0; nt < 8; nt++) {
            float p00 = exp2_(sacc[nt][0] - m0n), p01 = exp2_(sacc[nt][1] - m0n);
            float p10 = exp2_(sacc[nt][2] - m1n), p11 = exp2_(sacc[nt][3] - m1n);
            sum0 += p00 + p01; sum1 += p10 + p11;
            __nv_bfloat16 h00 = __float2bfloat16(p00), h01 = __float2bfloat16(p01);
            __nv_bfloat16 h10 = __float2bfloat16(p10), h11 = __float2bfloat16(p11);
            __nv_bfloat16 l00 = __float2bfloat16(p00 - __bfloat162float(h00));
            __nv_bfloat16 l01 = __float2bfloat16(p01 - __bfloat162float(h01));
            __nv_bfloat16 l10 = __float2bfloat16(p10 - __bfloat162float(h10));
            __nv_bfloat16 l11 = __float2bfloat16(p11 - __bfloat162float(h11));
            int cb = nt * 8 + tig * 2;
            *(__nv_bfloat162*)(fsm + FSM_P  + (m0 + gid)     * FPAD + cb) = __halves2bfloat162(h00, h01);
            *(__nv_bfloat162*)(fsm + FSM_P  + (m0 + gid + 8) * FPAD + cb) = __halves2bfloat162(h10, h11);
            *(__nv_bfloat162*)(fsm + FSM_PL + (m0 + gid)     * FPAD + cb) = __halves2bfloat162(l00, l01);
            *(__nv_bfloat162*)(fsm + FSM_PL + (m0 + gid + 8) * FPAD + cb) = __halves2bfloat162(l10, l11);
        }
        sum0 += __shfl_xor_sync(0xffffffffu, sum0, 1);
        sum0 += __shfl_xor_sync(0xffffffffu, sum0, 2);
        sum1 += __shfl_xor_sync(0xffffffffu, sum1, 1);
        sum1 += __shfl_xor_sync(0xffffffffu, sum1, 2);
        lsum0 = lsum0 * al0 + sum0;
        lsum1 = lsum1 * al1 + sum1;
        #pragma unroll
        for (int nt = 0; nt < 8; nt++) {
            oacc[nt][0] *= al0; oacc[nt][1] *= al0;
            oacc[nt][2] *= al1; oacc[nt][3] *= al1;
        }
        __syncwarp();

        #pragma unroll
        for (int kk = 0; kk < 4; kk++) {
            uint32_t aoff = (uint32_t)((m0 + arow) * FPAD + kk * 16 + akof) * 2;
            uint32_t Ph[4], Pl[4];
            ldsm_x4(Ph[0], Ph[1], Ph[2], Ph[3], bph + aoff);
            ldsm_x4(Pl[0], Pl[1], Pl[2], Pl[3], bpl + aoff);
            #pragma unroll
            for (int nt = 0; nt < 8; nt++) {
                uint32_t boff = (uint32_t)((nt * 8 + lr) * FPAD + kk * 16 + bkof) * 2;
                uint32_t bh0, bh1, bl0, bl1;
                ldsm_x2(bh0, bh1, bvh + boff);
                ldsm_x2(bl0, bl1, bvl + boff);
                mma16816(oacc[nt], Ph[0], Ph[1], Ph[2], Ph[3], bh0, bh1);
                mma16816(oacc[nt], Ph[0], Ph[1], Ph[2], Ph[3], bl0, bl1);
                mma16816(oacc[nt], Pl[0], Pl[1], Pl[2], Pl[3], bh0, bh1);
            }
        }
    }

    float inv0 = 1.f / lsum0, inv1 = 1.f / lsum1;
    size_t ob0 = ((size_t)(b * SS + qi0)) * DD + h * HD;
    size_t ob1 = ob0 + (size_t)8 * DD;
    #pragma unroll
    for (int nt = 0; nt < 8; nt++) {
        int cb = nt * 8 + tig * 2;
        float o00 = oacc[nt][0] * inv0, o01 = oacc[nt][1] * inv0;
        float o10 = oacc[nt][2] * inv1, o11 = oacc[nt][3] * inv1;
        __nv_bfloat16 h00 = __float2bfloat16(o00), h01 = __float2bfloat16(o01);
        __nv_bfloat16 h10 = __float2bfloat16(o10), h11 = __float2bfloat16(o11);
        __nv_bfloat16 l00 = __float2bfloat16(o00 - __bfloat162float(h00));
        __nv_bfloat16 l01 = __float2bfloat16(o01 - __bfloat162float(h01));
        __nv_bfloat16 l10 = __float2bfloat16(o10 - __bfloat162float(h10));
        __nv_bfloat16 l11 = __float2bfloat16(o11 - __bfloat162float(h11));
        *(__nv_bfloat162*)(g_atthi + ob0 + cb) = __halves2bfloat162(h00, h01);
        *(__nv_bfloat162*)(g_atthi + ob1 + cb) = __halves2bfloat162(h10, h11);
        *(__nv_bfloat162*)(g_attlo + ob0 + cb) = __halves2bfloat162(l00, l01);
        *(__nv_bfloat162*)(g_attlo + ob1 + cb) = __halves2bfloat162(l10, l11);
    }
}

// ---------------------------------------------------------------------------
extern "C" void kernel_launch(void* const* d_in, const int* in_sizes, int n_in,
                              void* d_out, int out_size)
{
    const float* x  = (const float*)d_in[0];
    const float* pc = (const float*)d_in[1];
    const float* ps = (const float*)d_in[2];
    const float* wq = (const float*)d_in[3];
    const float* bq = (const float*)d_in[4];
    const float* wk = (const float*)d_in[5];
    const float* bk = (const float*)d_in[6];
    const float* wv = (const float*)d_in[7];
    const float* bv = (const float*)d_in[8];
    const float* wo = (const float*)d_in[9];
    const float* bo = (const float*)d_in[10];
    float* out = (float*)d_out;

    cudaFuncSetAttribute(qkv_gemm, cudaFuncAttributeMaxDynamicSharedMemorySize, GEMM_SMEM_BYTES);
    cudaFuncSetAttribute(out_gemm, cudaFuncAttributeMaxDynamicSharedMemorySize, GEMM_SMEM_BYTES);
    cudaFuncSetAttribute(flash_mma_kernel, cudaFuncAttributeMaxDynamicSharedMemorySize, FLASH_SMEM_BYTES);

    __nv_bfloat16 *xhi_p, *xlo_p, *whi_p, *wlo_p;
    cudaGetSymbolAddress((void**)&xhi_p, g_xhi);
    cudaGetSymbolAddress((void**)&xlo_p, g_xlo);
    cudaGetSymbolAddress((void**)&whi_p, g_whi);
    cudaGetSymbolAddress((void**)&wlo_p, g_wlo);

    split_kernel<<<(MROWS*DD/4 + 255)/256, 256>>>(x, xhi_p, xlo_p, MROWS*DD/4);
    dim3 gws(DD*DD/4/256, 4);
    wsplit_kernel<<<gws, 256>>>(wq, wk, wv, wo, whi_p, wlo_p);

    dim3 gqkv(8, 32, 3);
    qkv_gemm<<<gqkv, 256, GEMM_SMEM_BYTES>>>(bq, bk, bv);

    rope_split_kernel<<<(MROWS * 512) / 256, 256>>>(pc, ps);

    dim3 gvt(SS / 32, HD / 32, BB * HH);
    vsplitT_kernel<<<gvt, dim3(32, 8)>>>();

    dim3 gfa(SS / 128, HH, BB);
    flash_mma_kernel<<<gfa, 256, FLASH_SMEM_BYTES>>>();

    dim3 gout(8, 32, 1);
    out_gemm<<<gout, 256, GEMM_SMEM_BYTES>>>(bo, out);
}

// round 14
// speedup vs baseline: 1.1369x; 1.1369x over previous
#include <cuda_runtime.h>
#include <cuda_bf16.h>
#include <cstdint>

#define BB   2
#define SS   2048
#define DD   1024
#define HH   16
#define HD   64
#define MROWS (BB*SS)   // 4096

// ---------------------------------------------------------------------------
// Scratch (__device__ globals; no allocation allowed)
// ---------------------------------------------------------------------------
__device__ float g_q[MROWS*DD];
__device__ float g_k[MROWS*DD];
__device__ float g_v[MROWS*DD];
__device__ __nv_bfloat16 g_xhi[MROWS*DD];
__device__ __nv_bfloat16 g_xlo[MROWS*DD];
__device__ __nv_bfloat16 g_whi[4*DD*DD];
__device__ __nv_bfloat16 g_wlo[4*DD*DD];
__device__ __nv_bfloat16 g_atthi[MROWS*DD];
__device__ __nv_bfloat16 g_attlo[MROWS*DD];
// flash operands
__device__ __nv_bfloat16 g_qhi[MROWS*DD];
__device__ __nv_bfloat16 g_qlo[MROWS*DD];
__device__ __nv_bfloat16 g_khi[MROWS*DD];
__device__ __nv_bfloat16 g_klo[MROWS*DD];
__device__ __nv_bfloat16 g_vthi[MROWS*DD];   // [(b*HH+h)*HD + d][s]
__device__ __nv_bfloat16 g_vtlo[MROWS*DD];

// ---------------------------------------------------------------------------
// PTX helpers (baseline ISA only — valid for plain sm_103 target)
// ---------------------------------------------------------------------------
__device__ __forceinline__ uint32_t smem_u32(const void* p) {
    uint32_t a;
    asm("{ .reg .u64 t; cvta.to.shared.u64 t, %1; cvt.u32.u64 %0, t; }" : "=r"(a) : "l"(p));
    return a;
}
__device__ __forceinline__ void cpa16(uint32_t saddr, const void* g) {
    asm volatile("cp.async.cg.shared.global [%0], [%1], 16;" :: "r"(saddr), "l"(g));
}
#define CP_COMMIT() asm volatile("cp.async.commit_group;" ::: "memory")
#define CP_WAIT0()  asm volatile("cp.async.wait_group 0;" ::: "memory")

__device__ __forceinline__ void ldsm_x4(uint32_t& r0, uint32_t& r1, uint32_t& r2,
                                        uint32_t& r3, uint32_t a) {
    asm volatile("ldmatrix.sync.aligned.m8n8.x4.shared.b16 {%0,%1,%2,%3}, [%4];"
                 : "=r"(r0), "=r"(r1), "=r"(r2), "=r"(r3) : "r"(a));
}
__device__ __forceinline__ void ldsm_x2(uint32_t& r0, uint32_t& r1, uint32_t a) {
    asm volatile("ldmatrix.sync.aligned.m8n8.x2.shared.b16 {%0,%1}, [%2];"
                 : "=r"(r0), "=r"(r1) : "r"(a));
}
__device__ __forceinline__ void mma16816(float* c, uint32_t a0, uint32_t a1,
                                         uint32_t a2, uint32_t a3,
                                         uint32_t b0, uint32_t b1) {
    asm volatile(
        "mma.sync.aligned.m16n8k16.row.col.f32.bf16.bf16.f32 "
        "{%0,%1,%2,%3}, {%4,%5,%6,%7}, {%8,%9}, {%0,%1,%2,%3};"
        : "+f"(c[0]), "+f"(c[1]), "+f"(c[2]), "+f"(c[3])
        : "r"(a0), "r"(a1), "r"(a2), "r"(a3), "r"(b0), "r"(b1));
}
__device__ __forceinline__ float exp2_(float x) {
    float y; asm("ex2.approx.f32 %0, %1;" : "=f"(y) : "f"(x)); return y;
}

// ---------------------------------------------------------------------------
// Split fp32 -> bf16 hi + bf16 lo
// ---------------------------------------------------------------------------
__device__ __forceinline__ void split4(const float* __restrict__ in,
                                       __nv_bfloat16* __restrict__ hi,
                                       __nv_bfloat16* __restrict__ lo, int i)
{
    float4 v = ((const float4*)in)[i];
    __nv_bfloat16 hx = __float2bfloat16(v.x);
    __nv_bfloat16 hy = __float2bfloat16(v.y);
    __nv_bfloat16 hz = __float2bfloat16(v.z);
    __nv_bfloat16 hw = __float2bfloat16(v.w);
    __nv_bfloat16 lx = __float2bfloat16(v.x - __bfloat162float(hx));
    __nv_bfloat16 ly = __float2bfloat16(v.y - __bfloat162float(hy));
    __nv_bfloat16 lz = __float2bfloat16(v.z - __bfloat162float(hz));
    __nv_bfloat16 lw = __float2bfloat16(v.w - __bfloat162float(hw));
    ((__nv_bfloat162*)hi)[2*i]   = __halves2bfloat162(hx, hy);
    ((__nv_bfloat162*)hi)[2*i+1] = __halves2bfloat162(hz, hw);
    ((__nv_bfloat162*)lo)[2*i]   = __halves2bfloat162(lx, ly);
    ((__nv_bfloat162*)lo)[2*i+1] = __halves2bfloat162(lz, lw);
}

__global__ __launch_bounds__(256) void split_kernel(
    const float* __restrict__ in, __nv_bfloat16* __restrict__ hi,
    __nv_bfloat16* __restrict__ lo, int n4)
{
    int i = blockIdx.x * blockDim.x + threadIdx.x;
    if (i >= n4) return;
    split4(in, hi, lo, i);
}

__global__ __launch_bounds__(256) void wsplit_kernel(
    const float* __restrict__ w0, const float* __restrict__ w1,
    const float* __restrict__ w2, const float* __restrict__ w3,
    __nv_bfloat16* __restrict__ hi, __nv_bfloat16* __restrict__ lo)
{
    int z = blockIdx.y;
    const float* w = (z == 0) ? w0 : (z == 1) ? w1 : (z == 2) ? w2 : w3;
    int i = blockIdx.x * blockDim.x + threadIdx.x;
    split4(w, hi + (size_t)z * DD * DD, lo + (size_t)z * DD * DD, i);
}

// ---------------------------------------------------------------------------
// GEMM rebuilt as a clone of the measured-fast flash structure:
// CTA tile 128x64, 8 warps, warp tile 16x64 (acc = 32 floats),
// KC=64 double-buffered cp.async. C = Ah*Bh + Ah*Bl + Al*Bh + bias.
// ---------------------------------------------------------------------------
#define GPAD     72
#define GA_E     (128*GPAD)                 // 9216 elems per A array
#define GB_E     (64*GPAD)                  // 4608 elems per B array
#define GSTAGE_E (2*GA_E + 2*GB_E)          // 27648 elems per stage
#define GEMM_SMEM_BYTES (2*GSTAGE_E*2)      // 110592 B
#define GKC      64
#define GNST     (DD/GKC)                   // 16 stages

__device__ __forceinline__ void g_load_stage(
    uint32_t smb, int st,
    const __nv_bfloat16* __restrict__ Ahg, const __nv_bfloat16* __restrict__ Alg,
    const __nv_bfloat16* __restrict__ Bhg, const __nv_bfloat16* __restrict__ Blg,
    int bm, int bn, int k0, int tid)
{
    const uint32_t sb = smb + (uint32_t)(st * GSTAGE_E) * 2;
    // A: 2 arrays x 128 rows x 8 chunks = 2048 chunks, 8 per thread
    #pragma unroll
    for (int i = 0; i < 8; i++) {
        int v = tid + i * 256;
        int arr = v >> 10, idx = v & 1023, row = idx >> 3, c = idx & 7;
        uint32_t sa = sb + (uint32_t)(arr * GA_E + row * GPAD + c * 8) * 2;
        const __nv_bfloat16* g = arr ? Alg : Ahg;
        cpa16(sa, g + (size_t)(bm + row) * DD + k0 + c * 8);
    }
    // B: 2 arrays x 64 rows x 8 chunks = 1024 chunks, 4 per thread
    #pragma unroll
    for (int i = 0; i < 4; i++) {
        int v = tid + i * 256;
        int arr = v >> 9, idx = v & 511, row = idx >> 3, c = idx & 7;
        uint32_t sa = sb + (uint32_t)(2 * GA_E + arr * GB_E + row * GPAD + c * 8) * 2;
        const __nv_bfloat16* g = arr ? Blg : Bhg;
        cpa16(sa, g + (size_t)(bn + row) * DD + k0 + c * 8);
    }
    CP_COMMIT();
}

__device__ __forceinline__ void gemm_body(
    const __nv_bfloat16* __restrict__ Ahg, const __nv_bfloat16* __restrict__ Alg,
    const __nv_bfloat16* __restrict__ Bhg, const __nv_bfloat16* __restrict__ Blg,
    const float* __restrict__ bias, float* __restrict__ C, int bm, int bn)
{
    extern __shared__ __nv_bfloat16 sm[];
    const uint32_t smb = smem_u32(sm);

    const int tid  = threadIdx.x;
    const int lane = tid & 31;
    const int wid  = tid >> 5;
    const int m0   = wid * 16;            // warp owns rows [m0, m0+16)

    // ldsm lane mappings (identical to flash)
    const int g3   = lane >> 3;
    const int lr   = lane & 7;
    const int arow = lr + ((g3 & 1) << 3);
    const int akof = (g3 & 2) << 2;
    const int brow = ((lane >> 4) << 3) + lr;     // combined n/k mapping for B x4
    const int bkof = ((lane >> 3) & 1) << 3;

    float acc[8][4];
    #pragma unroll
    for (int nt = 0; nt < 8; nt++)
        #pragma unroll
        for (int r = 0; r < 4; r++) acc[nt][r] = 0.f;

    g_load_stage(smb, 0, Ahg, Alg, Bhg, Blg, bm, bn, 0, tid);

    for (int t = 0; t < GNST; t++) {
        CP_WAIT0();
        __syncthreads();
        if (t + 1 < GNST)
            g_load_stage(smb, (t + 1) & 1, Ahg, Alg, Bhg, Blg, bm, bn, (t + 1) * GKC, tid);

        const uint32_t stb = smb + (uint32_t)((t & 1) * GSTAGE_E) * 2;
        const uint32_t tAh = stb;
        const uint32_t tAl = stb + (uint32_t)GA_E * 2;
        const uint32_t tBh = stb + (uint32_t)(2 * GA_E) * 2;
        const uint32_t tBl = stb + (uint32_t)(2 * GA_E + GB_E) * 2;

        #pragma unroll
        for (int kk = 0; kk < 4; kk++) {
            uint32_t aoff = (uint32_t)((m0 + arow) * GPAD + kk * 16 + akof) * 2;
            uint32_t Ah[4], Al[4];
            ldsm_x4(Ah[0], Ah[1], Ah[2], Ah[3], tAh + aoff);
            ldsm_x4(Al[0], Al[1], Al[2], Al[3], tAl + aoff);

            uint32_t Bh[8][2], Bl[8][2];
            #pragma unroll
            for (int np = 0; np < 4; np++) {
                uint32_t bo = (uint32_t)((np * 16 + brow) * GPAD + kk * 16 + bkof) * 2;
                ldsm_x4(Bh[2*np][0], Bh[2*np][1], Bh[2*np+1][0], Bh[2*np+1][1], tBh + bo);
                ldsm_x4(Bl[2*np][0], Bl[2*np][1], Bl[2*np+1][0], Bl[2*np+1][1], tBl + bo);
            }

            #pragma unroll
            for (int nt = 0; nt < 8; nt++)
                mma16816(acc[nt], Ah[0], Ah[1], Ah[2], Ah[3], Bh[nt][0], Bh[nt][1]);
            #pragma unroll
            for (int nt = 0; nt < 8; nt++)
                mma16816(acc[nt], Ah[0], Ah[1], Ah[2], Ah[3], Bl[nt][0], Bl[nt][1]);
            #pragma unroll
            for (int nt = 0; nt < 8; nt++)
                mma16816(acc[nt], Al[0], Al[1], Al[2], Al[3], Bh[nt][0], Bh[nt][1]);
        }
        __syncthreads();   // all warps done with stage t before its buffer refilled
    }

    const int gid = lane >> 2;
    const int tig = lane & 3;
    const int r0  = bm + m0 + gid;
    #pragma unroll
    for (int nt = 0; nt < 8; nt++) {
        int cc = bn + nt * 8 + tig * 2;
        float b0 = bias[cc], b1 = bias[cc + 1];
        *(float2*)&C[(size_t)r0 * DD + cc]       = make_float2(acc[nt][0] + b0, acc[nt][1] + b1);
        *(float2*)&C[(size_t)(r0 + 8) * DD + cc] = make_float2(acc[nt][2] + b0, acc[nt][3] + b1);
    }
}

// QKV: grid = (16, 32, 3)  — N blocks, M blocks, matrix
__global__ __launch_bounds__(256, 1) void qkv_gemm(
    const float* __restrict__ bq, const float* __restrict__ bk,
    const float* __restrict__ bv)
{
    const int z = blockIdx.z;
    const __nv_bfloat16* Bh = &g_whi[(size_t)z * DD * DD];
    const __nv_bfloat16* Bl = &g_wlo[(size_t)z * DD * DD];
    const float* bias = (z == 0) ? bq : (z == 1) ? bk : bv;
    float* C = (z == 0) ? g_q : (z == 1) ? g_k : g_v;
    gemm_body(g_xhi, g_xlo, Bh, Bl, bias, C, blockIdx.y * 128, blockIdx.x * 64);
}

// Output projection: grid = (16, 32)
__global__ __launch_bounds__(256, 1) void out_gemm(
    const float* __restrict__ bo, float* __restrict__ out)
{
    gemm_body(g_atthi, g_attlo, &g_whi[(size_t)3 * DD * DD], &g_wlo[(size_t)3 * DD * DD],
              bo, out, blockIdx.y * 128, blockIdx.x * 64);
}

// ---------------------------------------------------------------------------
// RoPE + bf16 hi/lo split of q,k. q pre-scaled by 1/sqrt(hd) * log2(e).
// ---------------------------------------------------------------------------
#define QSCALE 0.180336880111120429f   // 0.125 * log2(e)

__global__ __launch_bounds__(256) void rope_split_kernel(
    const float* __restrict__ pcos, const float* __restrict__ psin)
{
    int idx = blockIdx.x * blockDim.x + threadIdx.x;
    int n   = idx >> 9;
    int pid = idx & 511;
    int srow = n & (SS - 1);
    int f    = pid & 31;
    float c  = pcos[srow * 32 + f];
    float sn = psin[srow * 32 + f];
    size_t off = ((size_t)n << 9) + pid;

    float2 qv = ((const float2*)g_q)[off];
    float qr = fmaf(qv.x, c, -qv.y * sn) * QSCALE;
    float qi = fmaf(qv.x, sn,  qv.y * c) * QSCALE;
    __nv_bfloat16 qh0 = __float2bfloat16(qr), qh1 = __float2bfloat16(qi);
    __nv_bfloat16 ql0 = __float2bfloat16(qr - __bfloat162float(qh0));
    __nv_bfloat16 ql1 = __float2bfloat16(qi - __bfloat162float(qh1));
    ((__nv_bfloat162*)g_qhi)[off] = __halves2bfloat162(qh0, qh1);
    ((__nv_bfloat162*)g_qlo)[off] = __halves2bfloat162(ql0, ql1);

    float2 kv = ((const float2*)g_k)[off];
    float kr = fmaf(kv.x, c, -kv.y * sn);
    float ki = fmaf(kv.x, sn,  kv.y * c);
    __nv_bfloat16 kh0 = __float2bfloat16(kr), kh1 = __float2bfloat16(ki);
    __nv_bfloat16 kl0 = __float2bfloat16(kr - __bfloat162float(kh0));
    __nv_bfloat16 kl1 = __float2bfloat16(ki - __bfloat162float(kh1));
    ((__nv_bfloat162*)g_khi)[off] = __halves2bfloat162(kh0, kh1);
    ((__nv_bfloat162*)g_klo)[off] = __halves2bfloat162(kl0, kl1);
}

// ---------------------------------------------------------------------------
// V transpose + split: g_v[b][s][h*64+d] -> g_vt{hi,lo}[(b*HH+h)*64+d][s]
// ---------------------------------------------------------------------------
__global__ __launch_bounds__(256) void vsplitT_kernel()
{
    __shared__ float t[32][33];
    const int s0 = blockIdx.x * 32;
    const int d0 = blockIdx.y * 32;
    const int bh = blockIdx.z;
    const int b  = bh >> 4;
    const int h  = bh & 15;
    const int lane = threadIdx.x;
    const int wr   = threadIdx.y;

    #pragma unroll
    for (int i = 0; i < 4; i++) {
        int row = wr + i * 8;
        t[row][lane] = g_v[((size_t)(b * SS + s0 + row)) * DD + h * HD + d0 + lane];
    }
    __syncthreads();
    #pragma unroll
    for (int i = 0; i < 4; i++) {
        int drow = wr + i * 8;
        float v = t[lane][drow];
        __nv_bfloat16 hv = __float2bfloat16(v);
        __nv_bfloat16 lv = __float2bfloat16(v - __bfloat162float(hv));
        size_t oa = ((size_t)(bh * HD + d0 + drow)) * SS + s0 + lane;
        g_vthi[oa] = hv;
        g_vtlo[oa] = lv;
    }
}

// ---------------------------------------------------------------------------
// Flash attention via m16n8k16 bf16-split mma (proven R12 — unchanged).
// ---------------------------------------------------------------------------
#define FPAD   72
#define FSM_Q   0
#define FSM_QL  9216
#define FSM_KV  18432
#define KVS     4608
#define FSM_P   55296
#define FSM_PL  64512
#define FLASH_SMEM_BYTES ((64512 + 9216) * 2)   // 147456

__global__ __launch_bounds__(256, 1) void flash_mma_kernel()
{
    extern __shared__ __nv_bfloat16 fsm[];
    const uint32_t smb = smem_u32(fsm);
    const int tid  = threadIdx.x;
    const int lane = tid & 31;
    const int wid  = tid >> 5;
    const int mblk = (int)(gridDim.x - 1) - (int)blockIdx.x;
    const int h    = blockIdx.y;
    const int b    = blockIdx.z;

    {
        const size_t qoff = ((size_t)(b * SS + mblk * 128)) * DD + h * HD;
        #pragma unroll
        for (int i = 0; i < 8; i++) {
            int v = tid + i * 256;
            const __nv_bfloat16* src = (v < 1024) ? g_qhi : g_qlo;
            int idx = v & 1023, row = idx >> 3, c = idx & 7;
            uint32_t sa = smb + (uint32_t)((v >> 10) * 9216 + row * FPAD + c * 8) * 2;
            cpa16(sa, src + qoff + (size_t)row * DD + c * 8);
        }
    }

    const int T = 2 * mblk + 2;

    auto load_kv = [&](int t, int st) {
        const int n0 = t * 64;
        const uint32_t sb = smb + (uint32_t)(FSM_KV + st * 4 * KVS) * 2;
        const size_t koff = ((size_t)(b * SS + n0)) * DD + h * HD;
        const size_t voff = ((size_t)((b * HH + h) * HD)) * SS + n0;
        #pragma unroll
        for (int i = 0; i < 8; i++) {
            int v = tid + i * 256;
            int arr = v >> 9, idx = v & 511, row = idx >> 3, c = idx & 7;
            uint32_t sa = sb + (uint32_t)(arr * KVS + row * FPAD + c * 8) * 2;
            const __nv_bfloat16* g;
            size_t ga;
            if (arr == 0)      { g = g_khi;  ga = koff + (size_t)row * DD + c * 8; }
            else if (arr == 1) { g = g_klo;  ga = koff + (size_t)row * DD + c * 8; }
            else if (arr == 2) { g = g_vthi; ga = voff + (size_t)row * SS + c * 8; }
            else               { g = g_vtlo; ga = voff + (size_t)row * SS + c * 8; }
            cpa16(sa, g + ga);
        }
        CP_COMMIT();
    };

    load_kv(0, 0);

    const int g3   = lane >> 3;
    const int lr   = lane & 7;
    const int arow = lr + ((g3 & 1) << 3);
    const int akof = (g3 & 2) << 2;
    const int bkof = ((lane >> 3) & 1) << 3;
    const int gid  = lane >> 2;
    const int tig  = lane & 3;
    const int m0   = wid * 16;
    const int qi0  = mblk * 128 + m0 + gid;

    float oacc[8][4];
    #pragma unroll
    for (int nt = 0; nt < 8; nt++)
        #pragma unroll
        for (int r = 0; r < 4; r++) oacc[nt][r] = 0.f;
    float mrow0 = -1e30f, mrow1 = -1e30f, lsum0 = 0.f, lsum1 = 0.f;

    const uint32_t bq  = smb;
    const uint32_t bql = smb + (uint32_t)FSM_QL * 2;
    const uint32_t bph = smb + (uint32_t)FSM_P * 2;
    const uint32_t bpl = smb + (uint32_t)FSM_PL * 2;

    for (int t = 0; t < T; t++) {
        CP_WAIT0();
        __syncthreads();
        const int st = t & 1;
        const uint32_t sb  = smb + (uint32_t)(FSM_KV + st * 4 * KVS) * 2;
        const uint32_t bkh = sb;
        const uint32_t bkl = sb + (uint32_t)KVS * 2;
        const uint32_t bvh = sb + (uint32_t)(2 * KVS) * 2;
        const uint32_t bvl = sb + (uint32_t)(3 * KVS) * 2;

        float sacc[8][4];
        #pragma unroll
        for (int nt = 0; nt < 8; nt++)
            #pragma unroll
            for (int r = 0; r < 4; r++) sacc[nt][r] = 0.f;

        #pragma unroll
        for (int kk = 0; kk < 4; kk++) {
            uint32_t aoff = (uint32_t)((m0 + arow) * FPAD + kk * 16 + akof) * 2;
            uint32_t Ah[4], Al[4];
            ldsm_x4(Ah[0], Ah[1], Ah[2], Ah[3], bq  + aoff);
            ldsm_x4(Al[0], Al[1], Al[2], Al[3], bql + aoff);
            #pragma unroll
            for (int nt = 0; nt < 8; nt++) {
                uint32_t boff = (uint32_t)((nt * 8 + lr) * FPAD + kk * 16 + bkof) * 2;
                uint32_t bh0, bh1, bl0, bl1;
                ldsm_x2(bh0, bh1, bkh + boff);
                ldsm_x2(bl0, bl1, bkl + boff);
                mma16816(sacc[nt], Ah[0], Ah[1], Ah[2], Ah[3], bh0, bh1);
                mma16816(sacc[nt], Ah[0], Ah[1], Ah[2], Ah[3], bl0, bl1);
                mma16816(sacc[nt], Al[0], Al[1], Al[2], Al[3], bh0, bh1);
            }
        }

        if (t + 1 < T) load_kv(t + 1, st ^ 1);

        const int n0 = t * 64;
        if (t >= 2 * mblk) {
            #pragma unroll
            for (int nt = 0; nt < 8; nt++) {
                int c0 = n0 + nt * 8 + tig * 2;
                if (c0     > qi0)     sacc[nt][0] = -1e30f;
                if (c0 + 1 > qi0)     sacc[nt][1] = -1e30f;
                if (c0     > qi0 + 8) sacc[nt][2] = -1e30f;
                if (c0 + 1 > qi0 + 8) sacc[nt][3] = -1e30f;
            }
        }

        float r0 = -1e30f, r1 = -1e30f;
        #pragma unroll
        for (int nt = 0; nt < 8; nt++) {
            r0 = fmaxf(r0, fmaxf(sacc[nt][0], sacc[nt][1]));
            r1 = fmaxf(r1, fmaxf(sacc[nt][2], sacc[nt][3]));
        }
        r0 = fmaxf(r0, __shfl_xor_sync(0xffffffffu, r0, 1));
        r0 = fmaxf(r0, __shfl_xor_sync(0xffffffffu, r0, 2));
        r1 = fmaxf(r1, __shfl_xor_sync(0xffffffffu, r1, 1));
        r1 = fmaxf(r1, __shfl_xor_sync(0xffffffffu, r1, 2));
        float m0n = fmaxf(mrow0, r0), m1n = fmaxf(mrow1, r1);
        float al0 = exp2_(mrow0 - m0n), al1 = exp2_(mrow1 - m1n);
        mrow0 = m0n; mrow1 = m1n;

        float sum0 = 0.f, sum1 = 0.f;
        #pragma unroll
        for (int nt = 0; nt < 8; nt++) {
            float p00 = exp2_(sacc[nt][0] - m0n), p01 = exp2_(sacc[nt][1] - m0n);
            float p10 = exp2_(sacc[nt][2] - m1n), p11 = exp2_(sacc[nt][3] - m1n);
            sum0 += p00 + p01; sum1 += p10 + p11;
            __nv_bfloat16 h00 = __float2bfloat16(p00), h01 = __float2bfloat16(p01);
            __nv_bfloat16 h10 = __float2bfloat16(p10), h11 = __float2bfloat16(p11);
            __nv_bfloat16 l00 = __float2bfloat16(p00 - __bfloat162float(h00));
            __nv_bfloat16 l01 = __float2bfloat16(p01 - __bfloat162float(h01));
            __nv_bfloat16 l10 = __float2bfloat16(p10 - __bfloat162float(h10));
            __nv_bfloat16 l11 = __float2bfloat16(p11 - __bfloat162float(h11));
            int cb = nt * 8 + tig * 2;
            *(__nv_bfloat162*)(fsm + FSM_P  + (m0 + gid)     * FPAD + cb) = __halves2bfloat162(h00, h01);
            *(__nv_bfloat162*)(fsm + FSM_P  + (m0 + gid + 8) * FPAD + cb) = __halves2bfloat162(h10, h11);
            *(__nv_bfloat162*)(fsm + FSM_PL + (m0 + gid)     * FPAD + cb) = __halves2bfloat162(l00, l01);
            *(__nv_bfloat162*)(fsm + FSM_PL + (m0 + gid + 8) * FPAD + cb) = __halves2bfloat162(l10, l11);
        }
        sum0 += __shfl_xor_sync(0xffffffffu, sum0, 1);
        sum0 += __shfl_xor_sync(0xffffffffu, sum0, 2);
        sum1 += __shfl_xor_sync(0xffffffffu, sum1, 1);
        sum1 += __shfl_xor_sync(0xffffffffu, sum1, 2);
        lsum0 = lsum0 * al0 + sum0;
        lsum1 = lsum1 * al1 + sum1;
        #pragma unroll
        for (int nt = 0; nt < 8; nt++) {
            oacc[nt][0] *= al0; oacc[nt][1] *= al0;
            oacc[nt][2] *= al1; oacc[nt][3] *= al1;
        }
        __syncwarp();

        #pragma unroll
        for (int kk = 0; kk < 4; kk++) {
            uint32_t aoff = (uint32_t)((m0 + arow) * FPAD + kk * 16 + akof) * 2;
            uint32_t Ph[4], Pl[4];
            ldsm_x4(Ph[0], Ph[1], Ph[2], Ph[3], bph + aoff);
            ldsm_x4(Pl[0], Pl[1], Pl[2], Pl[3], bpl + aoff);
            #pragma unroll
            for (int nt = 0; nt < 8; nt++) {
                uint32_t boff = (uint32_t)((nt * 8 + lr) * FPAD + kk * 16 + bkof) * 2;
                uint32_t bh0, bh1, bl0, bl1;
                ldsm_x2(bh0, bh1, bvh + boff);
                ldsm_x2(bl0, bl1, bvl + boff);
                mma16816(oacc[nt], Ph[0], Ph[1], Ph[2], Ph[3], bh0, bh1);
                mma16816(oacc[nt], Ph[0], Ph[1], Ph[2], Ph[3], bl0, bl1);
                mma16816(oacc[nt], Pl[0], Pl[1], Pl[2], Pl[3], bh0, bh1);
            }
        }
    }

    float inv0 = 1.f / lsum0, inv1 = 1.f / lsum1;
    size_t ob0 = ((size_t)(b * SS + qi0)) * DD + h * HD;
    size_t ob1 = ob0 + (size_t)8 * DD;
    #pragma unroll
    for (int nt = 0; nt < 8; nt++) {
        int cb = nt * 8 + tig * 2;
        float o00 = oacc[nt][0] * inv0, o01 = oacc[nt][1] * inv0;
        float o10 = oacc[nt][2] * inv1, o11 = oacc[nt][3] * inv1;
        __nv_bfloat16 h00 = __float2bfloat16(o00), h01 = __float2bfloat16(o01);
        __nv_bfloat16 h10 = __float2bfloat16(o10), h11 = __float2bfloat16(o11);
        __nv_bfloat16 l00 = __float2bfloat16(o00 - __bfloat162float(h00));
        __nv_bfloat16 l01 = __float2bfloat16(o01 - __bfloat162float(h01));
        __nv_bfloat16 l10 = __float2bfloat16(o10 - __bfloat162float(h10));
        __nv_bfloat16 l11 = __float2bfloat16(o11 - __bfloat162float(h11));
        *(__nv_bfloat162*)(g_atthi + ob0 + cb) = __halves2bfloat162(h00, h01);
        *(__nv_bfloat162*)(g_atthi + ob1 + cb) = __halves2bfloat162(h10, h11);
        *(__nv_bfloat162*)(g_attlo + ob0 + cb) = __halves2bfloat162(l00, l01);
        *(__nv_bfloat162*)(g_attlo + ob1 + cb) = __halves2bfloat162(l10, l11);
    }
}

// ---------------------------------------------------------------------------
extern "C" void kernel_launch(void* const* d_in, const int* in_sizes, int n_in,
                              void* d_out, int out_size)
{
    const float* x  = (const float*)d_in[0];
    const float* pc = (const float*)d_in[1];
    const float* ps = (const float*)d_in[2];
    const float* wq = (const float*)d_in[3];
    const float* bq = (const float*)d_in[4];
    const float* wk = (const float*)d_in[5];
    const float* bk = (const float*)d_in[6];
    const float* wv = (const float*)d_in[7];
    const float* bv = (const float*)d_in[8];
    const float* wo = (const float*)d_in[9];
    const float* bo = (const float*)d_in[10];
    float* out = (float*)d_out;

    cudaFuncSetAttribute(qkv_gemm, cudaFuncAttributeMaxDynamicSharedMemorySize, GEMM_SMEM_BYTES);
    cudaFuncSetAttribute(out_gemm, cudaFuncAttributeMaxDynamicSharedMemorySize, GEMM_SMEM_BYTES);
    cudaFuncSetAttribute(flash_mma_kernel, cudaFuncAttributeMaxDynamicSharedMemorySize, FLASH_SMEM_BYTES);

    __nv_bfloat16 *xhi_p, *xlo_p, *whi_p, *wlo_p;
    cudaGetSymbolAddress((void**)&xhi_p, g_xhi);
    cudaGetSymbolAddress((void**)&xlo_p, g_xlo);
    cudaGetSymbolAddress((void**)&whi_p, g_whi);
    cudaGetSymbolAddress((void**)&wlo_p, g_wlo);

    split_kernel<<<(MROWS*DD/4 + 255)/256, 256>>>(x, xhi_p, xlo_p, MROWS*DD/4);
    dim3 gws(DD*DD/4/256, 4);
    wsplit_kernel<<<gws, 256>>>(wq, wk, wv, wo, whi_p, wlo_p);

    dim3 gqkv(16, 32, 3);
    qkv_gemm<<<gqkv, 256, GEMM_SMEM_BYTES>>>(bq, bk, bv);

    rope_split_kernel<<<(MROWS * 512) / 256, 256>>>(pc, ps);

    dim3 gvt(SS / 32, HD / 32, BB * HH);
    vsplitT_kernel<<<gvt, dim3(32, 8)>>>();

    dim3 gfa(SS / 128, HH, BB);
    flash_mma_kernel<<<gfa, 256, FLASH_SMEM_BYTES>>>();

    dim3 gout(16, 32, 1);
    out_gemm<<<gout, 256, GEMM_SMEM_BYTES>>>(bo, out);
}